// round 1
// baseline (speedup 1.0000x reference)
#include <cuda_runtime.h>
#include <math.h>

#define Bn    2048
#define Tn    8
#define CIN   2048
#define CH    1024
#define Mn    32
#define NCLS  21
#define Jn    672        // NCLS * Mn
#define EPSv  1e-8f

// ---------------- scratch (device globals; no allocation allowed) ----------------
__device__ float g_sfT[Jn * CIN];   // (j=n*32+m, c) transposed static_feat
__device__ float g_Ek [Jn * CH];    // Ek rows (j,o); normalized in place -> Ekn
__device__ float g_Ev [Jn * CH];    // Ev rows (j,o)
__device__ float g_q  [Jn];         // q[j] = Ev[j,:].Ww
__device__ float g_k  [Bn * CH];
__device__ float g_v  [Bn * CH];
__device__ float g_ikn[Bn];         // 1/max(||k[b]||, eps)
__device__ float g_att[Bn * Jn];    // cos, then (in place) g = fw*w
__device__ float g_fE [Bn * CH];

// ---------------- transpose static_feat (n,c,m) -> sfT (n*32+m, c) ----------------
__global__ void transpose_sf(const float* __restrict__ sf) {
    __shared__ float tile[32][33];
    int n  = blockIdx.y;
    int c0 = blockIdx.x * 32;
    // coalesced read along m
    tile[threadIdx.y][threadIdx.x] = sf[((size_t)n * CIN + (c0 + threadIdx.y)) * Mn + threadIdx.x];
    __syncthreads();
    // coalesced write along c
    g_sfT[((size_t)(n * Mn + threadIdx.y)) * CIN + c0 + threadIdx.x] = tile[threadIdx.x][threadIdx.y];
}

// ---------------- tiled SGEMM: C = A @ op(B) + bias ----------------
// TRANSB=true : C[i,j] = sum_k A[i*lda+k]*B[j*ldb+k]   (B is N x K row-major)
// TRANSB=false: C[i,j] = sum_k A[i*lda+k]*B[k*ldb+j]   (B is K x N row-major)
// blockIdx.z selects (B,bias,C) pair so two GEMMs share one launch.
// Requires: K % 16 == 0, all row strides multiple of 4, bases 16B aligned, N % 4 == 0.
template <bool TRANSB>
__global__ __launch_bounds__(256)
void sgemm_kernel(const float* __restrict__ A, int lda,
                  const float* __restrict__ Bm0, const float* __restrict__ Bm1, int ldb,
                  const float* __restrict__ bias0, const float* __restrict__ bias1,
                  float* __restrict__ C0, float* __restrict__ C1, int ldc,
                  int Md, int Nd, int Kd)
{
    const float* Bm   = blockIdx.z ? Bm1   : Bm0;
    const float* bias = blockIdx.z ? bias1 : bias0;
    float*       C    = blockIdx.z ? C1    : C0;

    __shared__ float As[16][128];
    __shared__ float Bs[16][128];

    const int tid = threadIdx.x;
    const int bm0 = blockIdx.y * 128;
    const int bn0 = blockIdx.x * 128;
    const int tx = tid & 15, ty = tid >> 4;

    // loader mappings
    const int arow = tid >> 2;           // 0..63
    const int akk  = (tid & 3) * 4;      // 0,4,8,12
    const int bkk  = tid >> 4;           // 0..15 (NN)
    const int bcol = (tid & 15) * 4;     // 0..60 (NN)

    float acc[8][8];
#pragma unroll
    for (int i = 0; i < 8; i++)
#pragma unroll
        for (int j = 0; j < 8; j++) acc[i][j] = 0.f;

    for (int k0 = 0; k0 < Kd; k0 += 16) {
#pragma unroll
        for (int h = 0; h < 2; h++) {
            int r = arow + h * 64;
            int gr = bm0 + r;
            float4 val = make_float4(0.f, 0.f, 0.f, 0.f);
            if (gr < Md) val = *(const float4*)&A[(size_t)gr * lda + k0 + akk];
            As[akk + 0][r] = val.x; As[akk + 1][r] = val.y;
            As[akk + 2][r] = val.z; As[akk + 3][r] = val.w;
        }
        if (TRANSB) {
#pragma unroll
            for (int h = 0; h < 2; h++) {
                int r = arow + h * 64;
                int gc = bn0 + r;
                float4 val = make_float4(0.f, 0.f, 0.f, 0.f);
                if (gc < Nd) val = *(const float4*)&Bm[(size_t)gc * ldb + k0 + akk];
                Bs[akk + 0][r] = val.x; Bs[akk + 1][r] = val.y;
                Bs[akk + 2][r] = val.z; Bs[akk + 3][r] = val.w;
            }
        } else {
#pragma unroll
            for (int h = 0; h < 2; h++) {
                int c = bcol + h * 64;
                int gc = bn0 + c;
                float4 val = make_float4(0.f, 0.f, 0.f, 0.f);
                if (gc < Nd) val = *(const float4*)&Bm[(size_t)(k0 + bkk) * ldb + gc];
                *(float4*)&Bs[bkk][c] = val;
            }
        }
        __syncthreads();

#pragma unroll
        for (int kk = 0; kk < 16; kk++) {
            float4 a0 = *(const float4*)&As[kk][ty * 4];
            float4 a1 = *(const float4*)&As[kk][ty * 4 + 64];
            float4 b0 = *(const float4*)&Bs[kk][tx * 4];
            float4 b1 = *(const float4*)&Bs[kk][tx * 4 + 64];
            float av[8] = {a0.x, a0.y, a0.z, a0.w, a1.x, a1.y, a1.z, a1.w};
            float bv[8] = {b0.x, b0.y, b0.z, b0.w, b1.x, b1.y, b1.z, b1.w};
#pragma unroll
            for (int i = 0; i < 8; i++)
#pragma unroll
                for (int j = 0; j < 8; j++) acc[i][j] += av[i] * bv[j];
        }
        __syncthreads();
    }

#pragma unroll
    for (int i = 0; i < 8; i++) {
        int r = bm0 + ((i < 4) ? (ty * 4 + i) : (64 + ty * 4 + (i - 4)));
        if (r >= Md) continue;
#pragma unroll
        for (int j = 0; j < 8; j++) {
            int c = bn0 + ((j < 4) ? (tx * 4 + j) : (64 + tx * 4 + (j - 4)));
            if (c >= Nd) continue;
            float o = acc[i][j];
            if (bias) o += bias[c];
            C[(size_t)r * ldc + c] = o;
        }
    }
}

// ---------------- normalize Ek rows (over o) + q[j] = Ev[j,:].Ww ----------------
__global__ void prep_rows(const float* __restrict__ Ww) {
    int j = blockIdx.x;
    float* ek = g_Ek + (size_t)j * CH;
    const float* ev = g_Ev + (size_t)j * CH;
    float ss = 0.f, dq = 0.f;
    for (int o = threadIdx.x; o < CH; o += 256) {
        float e = ek[o];
        ss += e * e;
        dq += ev[o] * Ww[o];
    }
#pragma unroll
    for (int off = 16; off; off >>= 1) {
        ss += __shfl_xor_sync(0xffffffffu, ss, off);
        dq += __shfl_xor_sync(0xffffffffu, dq, off);
    }
    __shared__ float s1[8], s2[8];
    int lane = threadIdx.x & 31, w = threadIdx.x >> 5;
    if (lane == 0) { s1[w] = ss; s2[w] = dq; }
    __syncthreads();
    if (threadIdx.x == 0) {
        float a = 0.f, q = 0.f;
        for (int i = 0; i < 8; i++) { a += s1[i]; q += s2[i]; }
        s1[0] = 1.f / fmaxf(sqrtf(a), EPSv);
        g_q[j] = q;
    }
    __syncthreads();
    float inv = s1[0];
    for (int o = threadIdx.x; o < CH; o += 256) ek[o] *= inv;
}

// ---------------- 1/||k[b]|| ----------------
__global__ void knorm_kernel() {
    int b = blockIdx.x;
    const float* kr = g_k + (size_t)b * CH;
    float ss = 0.f;
    for (int o = threadIdx.x; o < CH; o += 256) { float t = kr[o]; ss += t * t; }
#pragma unroll
    for (int off = 16; off; off >>= 1) ss += __shfl_xor_sync(0xffffffffu, ss, off);
    __shared__ float s1[8];
    int lane = threadIdx.x & 31, w = threadIdx.x >> 5;
    if (lane == 0) s1[w] = ss;
    __syncthreads();
    if (threadIdx.x == 0) {
        float a = 0.f;
        for (int i = 0; i < 8; i++) a += s1[i];
        g_ikn[b] = 1.f / fmaxf(sqrtf(a), EPSv);
    }
}

// ---------------- per-row attention: softmax_m, logits via q, softmax_n, g=fw*w ----------------
__global__ void attn_kernel(const float* __restrict__ bw) {
    int b = blockIdx.x;
    int m = threadIdx.x;          // 32 (one warp per n)
    int n = threadIdx.y;          // 21
    int j = n * Mn + m;
    float inv = g_ikn[b];
    float c = g_att[(size_t)b * Jn + j] * inv;

    float mx = c;
#pragma unroll
    for (int off = 16; off; off >>= 1) mx = fmaxf(mx, __shfl_xor_sync(0xffffffffu, mx, off));
    float e = __expf(c - mx);
    float s = e;
#pragma unroll
    for (int off = 16; off; off >>= 1) s += __shfl_xor_sync(0xffffffffu, s, off);
    float w = e / s;

    float lq = w * g_q[j];
#pragma unroll
    for (int off = 16; off; off >>= 1) lq += __shfl_xor_sync(0xffffffffu, lq, off);

    __shared__ float sl[NCLS];
    if (m == 0) sl[n] = lq + bw[0];
    __syncthreads();

    float fmx = -1e30f;
#pragma unroll
    for (int i = 0; i < NCLS; i++) fmx = fmaxf(fmx, sl[i]);
    float fs = 0.f;
#pragma unroll
    for (int i = 0; i < NCLS; i++) fs += __expf(sl[i] - fmx);
    float fw = __expf(sl[n] - fmx) / fs;

    g_att[(size_t)b * Jn + j] = fw * w;
}

// ---------------- final: out[b,c] = relu(v).Wout[c,:CH] + relu(fE).Wout[c,CH:] + bout ----------------
__global__ void out_kernel(const float* __restrict__ Wout, const float* __restrict__ bout,
                           float* __restrict__ out) {
    int b = blockIdx.x;
    const float* vr = g_v  + (size_t)b * CH;
    const float* fr = g_fE + (size_t)b * CH;
    float acc[NCLS];
#pragma unroll
    for (int c = 0; c < NCLS; c++) acc[c] = 0.f;
    for (int o = threadIdx.x; o < CH; o += 256) {
        float rv = fmaxf(vr[o], 0.f);
        float rf = fmaxf(fr[o], 0.f);
#pragma unroll
        for (int c = 0; c < NCLS; c++)
            acc[c] += rv * Wout[(size_t)c * (2 * CH) + o] + rf * Wout[(size_t)c * (2 * CH) + CH + o];
    }
    __shared__ float sh[8][NCLS];
    int lane = threadIdx.x & 31, w = threadIdx.x >> 5;
#pragma unroll
    for (int c = 0; c < NCLS; c++) {
        float vsum = acc[c];
#pragma unroll
        for (int off = 16; off; off >>= 1) vsum += __shfl_xor_sync(0xffffffffu, vsum, off);
        if (lane == 0) sh[w][c] = vsum;
    }
    __syncthreads();
    if (threadIdx.x < NCLS) {
        float s = 0.f;
        for (int wi = 0; wi < 8; wi++) s += sh[wi][threadIdx.x];
        out[(size_t)b * NCLS + threadIdx.x] = s + bout[threadIdx.x];
    }
}

// ---------------- host launcher ----------------
extern "C" void kernel_launch(void* const* d_in, const int* in_sizes, int n_in,
                              void* d_out, int out_size) {
    const float* x    = (const float*)d_in[0];
    const float* sf   = (const float*)d_in[1];
    const float* Wk   = (const float*)d_in[2];
    const float* bk   = (const float*)d_in[3];
    const float* Wv   = (const float*)d_in[4];
    const float* bv   = (const float*)d_in[5];
    const float* WEk  = (const float*)d_in[6];
    const float* bEk  = (const float*)d_in[7];
    const float* WEv  = (const float*)d_in[8];
    const float* bEv  = (const float*)d_in[9];
    const float* Ww   = (const float*)d_in[10];
    const float* bw   = (const float*)d_in[11];
    const float* Wout = (const float*)d_in[12];
    const float* bout = (const float*)d_in[13];
    float* out = (float*)d_out;

    float *p_sfT, *p_Ek, *p_Ev, *p_k, *p_v, *p_att, *p_fE;
    cudaGetSymbolAddress((void**)&p_sfT, g_sfT);
    cudaGetSymbolAddress((void**)&p_Ek,  g_Ek);
    cudaGetSymbolAddress((void**)&p_Ev,  g_Ev);
    cudaGetSymbolAddress((void**)&p_k,   g_k);
    cudaGetSymbolAddress((void**)&p_v,   g_v);
    cudaGetSymbolAddress((void**)&p_att, g_att);
    cudaGetSymbolAddress((void**)&p_fE,  g_fE);

    // 1) transpose static_feat
    transpose_sf<<<dim3(CIN / 32, NCLS), dim3(32, 32)>>>(sf);

    // 2) Ek/Ev = sfT @ WE.T + bE   (672 x 1024, K=2048), z=2
    sgemm_kernel<true><<<dim3(CH / 128, (Jn + 127) / 128, 2), 256>>>(
        p_sfT, CIN, WEk, WEv, CIN, bEk, bEv, p_Ek, p_Ev, CH, Jn, CH, CIN);

    // 3) k/v = xl @ W.T + b   (2048 x 1024, K=2048), z=2; xl rows stride T*CIN, t=T-1
    sgemm_kernel<true><<<dim3(CH / 128, Bn / 128, 2), 256>>>(
        x + (size_t)(Tn - 1) * CIN, Tn * CIN, Wk, Wv, CIN, bk, bv, p_k, p_v, CH, Bn, CH, CIN);

    // 4) normalize Ek rows, q[j]
    prep_rows<<<Jn, 256>>>(Ww);

    // 5) 1/||k[b]||
    knorm_kernel<<<Bn, 256>>>();

    // 6) cos = k @ Ekn.T   (2048 x 672, K=1024)
    sgemm_kernel<true><<<dim3((Jn + 127) / 128, Bn / 128, 1), 256>>>(
        p_k, CH, p_Ek, p_Ek, CH, nullptr, nullptr, p_att, p_att, Jn, Bn, Jn, CH);

    // 7) softmaxes + g = fw*w (in place on g_att)
    attn_kernel<<<Bn, dim3(32, NCLS)>>>(bw);

    // 8) fE = g @ Ev   (2048 x 1024, K=672), NN form
    sgemm_kernel<false><<<dim3(CH / 128, Bn / 128, 1), 256>>>(
        p_att, Jn, p_Ev, p_Ev, CH, nullptr, nullptr, p_fE, p_fE, CH, Bn, CH, Jn);

    // 9) fused relu-concat + output projection
    out_kernel<<<Bn, 256>>>(Wout, bout, out);
}

// round 3
// speedup vs baseline: 2.1223x; 2.1223x over previous
#include <cuda_runtime.h>
#include <cuda_bf16.h>
#include <cstdint>
#include <math.h>

#define Bn    2048
#define Tn    8
#define CIN   2048
#define CH    1024
#define Mn    32
#define NCLS  21
#define Jn    672        // NCLS * Mn
#define EPSv  1e-8f

// ---------------- scratch (device globals; no allocation allowed) ----------------
__device__ float g_sfT[Jn * CIN];   // (j=n*32+m, c) transposed static_feat
__device__ float g_Ek [Jn * CH];    // Ek rows (j,o); normalized in place -> Ekn
__device__ float g_Ev [Jn * CH];    // Ev rows (j,o)
__device__ float g_q  [Jn];         // q[j] = Ev[j,:].Ww
__device__ float g_k  [Bn * CH];
__device__ float g_v  [Bn * CH];
__device__ float g_ikn[Bn];         // 1/max(||k[b]||, eps)
__device__ float g_att[Bn * Jn];    // cos, then (in place) g = fw*w
__device__ float g_fE [Bn * CH];

// ---------------- transpose static_feat (n,c,m) -> sfT (n*32+m, c) ----------------
__global__ void transpose_sf(const float* __restrict__ sf) {
    __shared__ float tile[32][33];
    int n  = blockIdx.y;
    int c0 = blockIdx.x * 32;
    tile[threadIdx.y][threadIdx.x] = sf[((size_t)n * CIN + (c0 + threadIdx.y)) * Mn + threadIdx.x];
    __syncthreads();
    g_sfT[((size_t)(n * Mn + threadIdx.y)) * CIN + c0 + threadIdx.x] = tile[threadIdx.x][threadIdx.y];
}

// ---------------- PTX helpers (scalar-reference style, proven to compile) ----------------
__device__ __forceinline__ void ldsm4(uint32_t &r0, uint32_t &r1, uint32_t &r2, uint32_t &r3,
                                      uint32_t addr) {
    asm volatile("ldmatrix.sync.aligned.m8n8.x4.shared.b16 {%0,%1,%2,%3}, [%4];"
                 : "=r"(r0), "=r"(r1), "=r"(r2), "=r"(r3) : "r"(addr));
}
__device__ __forceinline__ void ldsm4t(uint32_t &r0, uint32_t &r1, uint32_t &r2, uint32_t &r3,
                                       uint32_t addr) {
    asm volatile("ldmatrix.sync.aligned.m8n8.x4.trans.shared.b16 {%0,%1,%2,%3}, [%4];"
                 : "=r"(r0), "=r"(r1), "=r"(r2), "=r"(r3) : "r"(addr));
}
__device__ __forceinline__ void mma16816(float &c0, float &c1, float &c2, float &c3,
                                         uint32_t a0, uint32_t a1, uint32_t a2, uint32_t a3,
                                         uint32_t b0, uint32_t b1) {
    asm volatile("mma.sync.aligned.m16n8k16.row.col.f32.bf16.bf16.f32 "
                 "{%0,%1,%2,%3}, {%4,%5,%6,%7}, {%8,%9}, {%0,%1,%2,%3};"
                 : "+f"(c0), "+f"(c1), "+f"(c2), "+f"(c3)
                 : "r"(a0), "r"(a1), "r"(a2), "r"(a3), "r"(b0), "r"(b1));
}
// split fp32x4 into hi/lo bf16 and store 8B to each of two smem slots
__device__ __forceinline__ void splitst(__nv_bfloat16* hi, __nv_bfloat16* lo, float4 v) {
    __nv_bfloat162 h0 = __floats2bfloat162_rn(v.x, v.y);
    __nv_bfloat162 h1 = __floats2bfloat162_rn(v.z, v.w);
    __nv_bfloat162 l0 = __floats2bfloat162_rn(v.x - __low2float(h0), v.y - __high2float(h0));
    __nv_bfloat162 l1 = __floats2bfloat162_rn(v.z - __low2float(h1), v.w - __high2float(h1));
    *(__nv_bfloat162*)(hi)     = h0;
    *(__nv_bfloat162*)(hi + 2) = h1;
    *(__nv_bfloat162*)(lo)     = l0;
    *(__nv_bfloat162*)(lo + 2) = l1;
}

// =====================================================================
// bf16x3 tensor-core GEMM: C = A @ op(B) + bias  (fp32 in/out, ~fp32 acc)
// x = hi + lo (bf16);  acc += Ah*Bh + Ah*Bl + Al*Bh  (fp32 accumulate)
// TRANSB=true : B stored [N][K];  TRANSB=false: B stored [K][N].
// CTA tile 128x128, k-tile 32, 8 warps of 64x32, mma.m16n8k16.
// Requires K%32==0, rows 16B-aligned, N even. blockIdx.z picks pair.
// =====================================================================
#define AS_STR 40       // smem row stride (bf16) for [rows][32] tiles (80B, 16B-aligned)
#define BS_STR 136      // smem row stride for NN [32][128] tiles (272B, 16B-aligned)
#define SM_A_HI 0
#define SM_A_LO 5120
#define SM_B_HI 10240
#define SM_B_LO_T 15360
#define SM_B_LO_N 14592

#define LOADG(K0) do {                                                              \
    _Pragma("unroll")                                                               \
    for (int li = 0; li < 4; li++) {                                                \
        int aidx = tid + li * 256;                                                  \
        int ar = aidx >> 3, ac = (aidx & 7) << 2;                                   \
        float4 av = make_float4(0.f, 0.f, 0.f, 0.f);                                \
        if (bm0 + ar < Md) av = *(const float4*)&A[(size_t)(bm0 + ar) * lda + (K0) + ac]; \
        aR[li] = av;                                                                \
        float4 bv = make_float4(0.f, 0.f, 0.f, 0.f);                                \
        if (TRANSB) {                                                               \
            if (bn0 + ar < Nd) bv = *(const float4*)&Bm[(size_t)(bn0 + ar) * ldb + (K0) + ac]; \
        } else {                                                                    \
            int brx = aidx >> 5, bcx = (aidx & 31) << 2;                            \
            if (bn0 + bcx < Nd) bv = *(const float4*)&Bm[(size_t)((K0) + brx) * ldb + bn0 + bcx]; \
        }                                                                           \
        bR[li] = bv;                                                                \
    }                                                                               \
} while (0)

#define STORES() do {                                                               \
    _Pragma("unroll")                                                               \
    for (int si = 0; si < 4; si++) {                                                \
        int aidx = tid + si * 256;                                                  \
        int ar = aidx >> 3, ac = (aidx & 7) << 2;                                   \
        splitst(&sm[SM_A_HI + ar * AS_STR + ac], &sm[SM_A_LO + ar * AS_STR + ac], aR[si]); \
        if (TRANSB) {                                                               \
            splitst(&sm[SM_B_HI + ar * AS_STR + ac], &sm[SM_B_LO_T + ar * AS_STR + ac], bR[si]); \
        } else {                                                                    \
            int brx = aidx >> 5, bcx = (aidx & 31) << 2;                            \
            splitst(&sm[SM_B_HI + brx * BS_STR + bcx], &sm[SM_B_LO_N + brx * BS_STR + bcx], bR[si]); \
        }                                                                           \
    }                                                                               \
} while (0)

template <bool TRANSB>
__global__ __launch_bounds__(256)
void gemm_bf16x3(const float* __restrict__ A, int lda,
                 const float* __restrict__ Bm0, const float* __restrict__ Bm1, int ldb,
                 const float* __restrict__ bias0, const float* __restrict__ bias1,
                 float* __restrict__ C0, float* __restrict__ C1, int ldc,
                 int Md, int Nd, int Kd)
{
    const float* Bm   = blockIdx.z ? Bm1   : Bm0;
    const float* bias = blockIdx.z ? bias1 : bias0;
    float*       C    = blockIdx.z ? C1    : C0;

    __shared__ __nv_bfloat16 sm[20480];
    const uint32_t sbase = (uint32_t)__cvta_generic_to_shared(sm);

    const int tid  = threadIdx.x;
    const int lane = tid & 31;
    const int warp = tid >> 5;
    const int wm = (warp >> 2) * 64;
    const int wn = (warp & 3) * 32;
    const int bm0 = blockIdx.y * 128;
    const int bn0 = blockIdx.x * 128;

    float acc[4][4][4];
#pragma unroll
    for (int i = 0; i < 4; i++)
#pragma unroll
        for (int j = 0; j < 4; j++) {
            acc[i][j][0] = 0.f; acc[i][j][1] = 0.f; acc[i][j][2] = 0.f; acc[i][j][3] = 0.f;
        }

    float4 aR[4], bR[4];

    LOADG(0);

    for (int k0 = 0; k0 < Kd; k0 += 32) {
        STORES();
        __syncthreads();
        if (k0 + 32 < Kd) LOADG(k0 + 32);

#pragma unroll
        for (int kk = 0; kk < 32; kk += 16) {
            uint32_t Ah[4][4], Al[4][4], Bh[4][2], Bl[4][2];
#pragma unroll
            for (int mt = 0; mt < 4; mt++) {
                int aoff = (wm + mt * 16 + (lane & 15)) * AS_STR + kk + ((lane >> 4) << 3);
                ldsm4(Ah[mt][0], Ah[mt][1], Ah[mt][2], Ah[mt][3],
                      sbase + (uint32_t)(SM_A_HI + aoff) * 2u);
                ldsm4(Al[mt][0], Al[mt][1], Al[mt][2], Al[mt][3],
                      sbase + (uint32_t)(SM_A_LO + aoff) * 2u);
            }
#pragma unroll
            for (int ntp = 0; ntp < 2; ntp++) {
                if (TRANSB) {
                    int boff = (wn + ntp * 16 + (lane & 15)) * AS_STR + kk + ((lane >> 4) << 3);
                    ldsm4(Bh[2*ntp][0], Bh[2*ntp+1][0], Bh[2*ntp][1], Bh[2*ntp+1][1],
                          sbase + (uint32_t)(SM_B_HI + boff) * 2u);
                    ldsm4(Bl[2*ntp][0], Bl[2*ntp+1][0], Bl[2*ntp][1], Bl[2*ntp+1][1],
                          sbase + (uint32_t)(SM_B_LO_T + boff) * 2u);
                } else {
                    int boff = (kk + (lane & 15)) * BS_STR + wn + ntp * 16 + ((lane >> 4) << 3);
                    ldsm4t(Bh[2*ntp][0], Bh[2*ntp][1], Bh[2*ntp+1][0], Bh[2*ntp+1][1],
                           sbase + (uint32_t)(SM_B_HI + boff) * 2u);
                    ldsm4t(Bl[2*ntp][0], Bl[2*ntp][1], Bl[2*ntp+1][0], Bl[2*ntp+1][1],
                           sbase + (uint32_t)(SM_B_LO_N + boff) * 2u);
                }
            }
#pragma unroll
            for (int mt = 0; mt < 4; mt++)
#pragma unroll
                for (int nt = 0; nt < 4; nt++) {
                    mma16816(acc[mt][nt][0], acc[mt][nt][1], acc[mt][nt][2], acc[mt][nt][3],
                             Ah[mt][0], Ah[mt][1], Ah[mt][2], Ah[mt][3], Bh[nt][0], Bh[nt][1]);
                    mma16816(acc[mt][nt][0], acc[mt][nt][1], acc[mt][nt][2], acc[mt][nt][3],
                             Ah[mt][0], Ah[mt][1], Ah[mt][2], Ah[mt][3], Bl[nt][0], Bl[nt][1]);
                    mma16816(acc[mt][nt][0], acc[mt][nt][1], acc[mt][nt][2], acc[mt][nt][3],
                             Al[mt][0], Al[mt][1], Al[mt][2], Al[mt][3], Bh[nt][0], Bh[nt][1]);
                }
        }
        __syncthreads();
    }

    // epilogue
#pragma unroll
    for (int mt = 0; mt < 4; mt++)
#pragma unroll
        for (int nt = 0; nt < 4; nt++) {
            int r = bm0 + wm + mt * 16 + (lane >> 2);
            int cc = bn0 + wn + nt * 8 + ((lane & 3) << 1);
            if (cc < Nd) {
                float b0 = bias ? bias[cc]     : 0.f;
                float b1 = bias ? bias[cc + 1] : 0.f;
                if (r < Md) {
                    float2 o = make_float2(acc[mt][nt][0] + b0, acc[mt][nt][1] + b1);
                    *(float2*)&C[(size_t)r * ldc + cc] = o;
                }
                if (r + 8 < Md) {
                    float2 o = make_float2(acc[mt][nt][2] + b0, acc[mt][nt][3] + b1);
                    *(float2*)&C[(size_t)(r + 8) * ldc + cc] = o;
                }
            }
        }
}

// ---------------- normalize Ek rows (over o) + q[j] = Ev[j,:].Ww ----------------
__global__ void prep_rows(const float* __restrict__ Ww) {
    int j = blockIdx.x;
    float* ek = g_Ek + (size_t)j * CH;
    const float* ev = g_Ev + (size_t)j * CH;
    float ss = 0.f, dq = 0.f;
    for (int o = threadIdx.x; o < CH; o += 256) {
        float e = ek[o];
        ss += e * e;
        dq += ev[o] * Ww[o];
    }
#pragma unroll
    for (int off = 16; off; off >>= 1) {
        ss += __shfl_xor_sync(0xffffffffu, ss, off);
        dq += __shfl_xor_sync(0xffffffffu, dq, off);
    }
    __shared__ float s1[8], s2[8];
    int lane = threadIdx.x & 31, w = threadIdx.x >> 5;
    if (lane == 0) { s1[w] = ss; s2[w] = dq; }
    __syncthreads();
    if (threadIdx.x == 0) {
        float a = 0.f, q = 0.f;
        for (int i = 0; i < 8; i++) { a += s1[i]; q += s2[i]; }
        s1[0] = 1.f / fmaxf(sqrtf(a), EPSv);
        g_q[j] = q;
    }
    __syncthreads();
    float inv = s1[0];
    for (int o = threadIdx.x; o < CH; o += 256) ek[o] *= inv;
}

// ---------------- 1/||k[b]|| ----------------
__global__ void knorm_kernel() {
    int b = blockIdx.x;
    const float* kr = g_k + (size_t)b * CH;
    float ss = 0.f;
    for (int o = threadIdx.x; o < CH; o += 256) { float t = kr[o]; ss += t * t; }
#pragma unroll
    for (int off = 16; off; off >>= 1) ss += __shfl_xor_sync(0xffffffffu, ss, off);
    __shared__ float s1[8];
    int lane = threadIdx.x & 31, w = threadIdx.x >> 5;
    if (lane == 0) s1[w] = ss;
    __syncthreads();
    if (threadIdx.x == 0) {
        float a = 0.f;
        for (int i = 0; i < 8; i++) a += s1[i];
        g_ikn[b] = 1.f / fmaxf(sqrtf(a), EPSv);
    }
}

// ---------------- per-row attention: softmax_m, logits via q, softmax_n, g=fw*w ----------------
__global__ void attn_kernel(const float* __restrict__ bw) {
    int b = blockIdx.x;
    int m = threadIdx.x;          // 32 (one warp per n)
    int n = threadIdx.y;          // 21
    int j = n * Mn + m;
    float inv = g_ikn[b];
    float c = g_att[(size_t)b * Jn + j] * inv;

    float mx = c;
#pragma unroll
    for (int off = 16; off; off >>= 1) mx = fmaxf(mx, __shfl_xor_sync(0xffffffffu, mx, off));
    float e = __expf(c - mx);
    float s = e;
#pragma unroll
    for (int off = 16; off; off >>= 1) s += __shfl_xor_sync(0xffffffffu, s, off);
    float w = e / s;

    float lq = w * g_q[j];
#pragma unroll
    for (int off = 16; off; off >>= 1) lq += __shfl_xor_sync(0xffffffffu, lq, off);

    __shared__ float sl[NCLS];
    if (m == 0) sl[n] = lq + bw[0];
    __syncthreads();

    float fmx = -1e30f;
#pragma unroll
    for (int i = 0; i < NCLS; i++) fmx = fmaxf(fmx, sl[i]);
    float fs = 0.f;
#pragma unroll
    for (int i = 0; i < NCLS; i++) fs += __expf(sl[i] - fmx);
    float fw = __expf(sl[n] - fmx) / fs;

    g_att[(size_t)b * Jn + j] = fw * w;
}

// ---------------- final: out[b,c] = relu(v).Wout[c,:CH] + relu(fE).Wout[c,CH:] + bout ----------------
__global__ void out_kernel(const float* __restrict__ Wout, const float* __restrict__ bout,
                           float* __restrict__ out) {
    int b = blockIdx.x;
    const float* vr = g_v  + (size_t)b * CH;
    const float* fr = g_fE + (size_t)b * CH;
    float acc[NCLS];
#pragma unroll
    for (int c = 0; c < NCLS; c++) acc[c] = 0.f;
    for (int o = threadIdx.x; o < CH; o += 256) {
        float rv = fmaxf(vr[o], 0.f);
        float rf = fmaxf(fr[o], 0.f);
#pragma unroll
        for (int c = 0; c < NCLS; c++)
            acc[c] += rv * Wout[(size_t)c * (2 * CH) + o] + rf * Wout[(size_t)c * (2 * CH) + CH + o];
    }
    __shared__ float sh[8][NCLS];
    int lane = threadIdx.x & 31, w = threadIdx.x >> 5;
#pragma unroll
    for (int c = 0; c < NCLS; c++) {
        float vsum = acc[c];
#pragma unroll
        for (int off = 16; off; off >>= 1) vsum += __shfl_xor_sync(0xffffffffu, vsum, off);
        if (lane == 0) sh[w][c] = vsum;
    }
    __syncthreads();
    if (threadIdx.x < NCLS) {
        float s = 0.f;
        for (int wi = 0; wi < 8; wi++) s += sh[wi][threadIdx.x];
        out[(size_t)b * NCLS + threadIdx.x] = s + bout[threadIdx.x];
    }
}

// ---------------- host launcher ----------------
extern "C" void kernel_launch(void* const* d_in, const int* in_sizes, int n_in,
                              void* d_out, int out_size) {
    const float* x    = (const float*)d_in[0];
    const float* sf   = (const float*)d_in[1];
    const float* Wk   = (const float*)d_in[2];
    const float* bk   = (const float*)d_in[3];
    const float* Wv   = (const float*)d_in[4];
    const float* bv   = (const float*)d_in[5];
    const float* WEk  = (const float*)d_in[6];
    const float* bEk  = (const float*)d_in[7];
    const float* WEv  = (const float*)d_in[8];
    const float* bEv  = (const float*)d_in[9];
    const float* Ww   = (const float*)d_in[10];
    const float* bw   = (const float*)d_in[11];
    const float* Wout = (const float*)d_in[12];
    const float* bout = (const float*)d_in[13];
    float* out = (float*)d_out;

    float *p_sfT, *p_Ek, *p_Ev, *p_k, *p_v, *p_att, *p_fE;
    cudaGetSymbolAddress((void**)&p_sfT, g_sfT);
    cudaGetSymbolAddress((void**)&p_Ek,  g_Ek);
    cudaGetSymbolAddress((void**)&p_Ev,  g_Ev);
    cudaGetSymbolAddress((void**)&p_k,   g_k);
    cudaGetSymbolAddress((void**)&p_v,   g_v);
    cudaGetSymbolAddress((void**)&p_att, g_att);
    cudaGetSymbolAddress((void**)&p_fE,  g_fE);

    // 1) transpose static_feat
    transpose_sf<<<dim3(CIN / 32, NCLS), dim3(32, 32)>>>(sf);

    // 2) Ek/Ev = sfT @ WE.T + bE   (672 x 1024, K=2048), z=2
    gemm_bf16x3<true><<<dim3(CH / 128, (Jn + 127) / 128, 2), 256>>>(
        p_sfT, CIN, WEk, WEv, CIN, bEk, bEv, p_Ek, p_Ev, CH, Jn, CH, CIN);

    // 3) k/v = xl @ W.T + b   (2048 x 1024, K=2048), z=2
    gemm_bf16x3<true><<<dim3(CH / 128, Bn / 128, 2), 256>>>(
        x + (size_t)(Tn - 1) * CIN, Tn * CIN, Wk, Wv, CIN, bk, bv, p_k, p_v, CH, Bn, CH, CIN);

    // 4) normalize Ek rows, q[j]
    prep_rows<<<Jn, 256>>>(Ww);

    // 5) 1/||k[b]||
    knorm_kernel<<<Bn, 256>>>();

    // 6) cos = k @ Ekn.T   (2048 x 672, K=1024)
    gemm_bf16x3<true><<<dim3((Jn + 127) / 128, Bn / 128, 1), 256>>>(
        p_k, CH, p_Ek, p_Ek, CH, nullptr, nullptr, p_att, p_att, Jn, Bn, Jn, CH);

    // 7) softmaxes + g = fw*w (in place on g_att)
    attn_kernel<<<Bn, dim3(32, NCLS)>>>(bw);

    // 8) fE = g @ Ev   (2048 x 1024, K=672), NN form
    gemm_bf16x3<false><<<dim3(CH / 128, Bn / 128, 1), 256>>>(
        p_att, Jn, p_Ev, p_Ev, CH, nullptr, nullptr, p_fE, p_fE, CH, Bn, CH, Jn);

    // 9) fused relu-concat + output projection
    out_kernel<<<Bn, 256>>>(Wout, bout, out);
}